// round 3
// baseline (speedup 1.0000x reference)
#include <cuda_runtime.h>
#include <math.h>
#include <stdint.h>

#define CDIV(a,b) (((a)+(b)-1)/(b))
#define B_   64
#define L_   20
#define H_   300
#define P_   8
#define N_   32768
#define E_   262144
#define C_   2048
#define OUT_ 1845
#define LDSIM 2052

__device__ __align__(16) float g_qt[B_*L_*H_];
__device__ __align__(16) float g_sim[B_*L_*LDSIM];
__device__ __align__(16) float g_vextT[H_*LDSIM];
__device__ __align__(16) float g_tagged[B_*L_*H_];
__device__ __align__(16) float g_Zx[B_*L_*1200];
__device__ __align__(16) float g_h[B_*H_];
__device__ __align__(16) float g_hidden[B_*4*H_];
__device__ __align__(16) float g_instr[B_*4*H_];
__device__ __align__(16) float g_npsim[B_*P_];
__device__ __align__(16) float g_rsim[B_];
__device__ __align__(16) float g_dist[N_];
__device__ __align__(16) float g_dotns[N_];
__device__ __align__(16) float g_dotnr[N_];
__device__ __align__(16) float g_agg[B_*H_];
__device__ __align__(16) float g_WihT[H_*1200];
__device__ __align__(16) float g_WhhT[H_*1200];
__device__ __align__(16) float g_rWihT[H_*H_];
__device__ __align__(16) float g_rWhhT[H_*H_];
__device__ __align__(16) float g_fc1T[600*600];
__device__ __align__(16) float g_fc2T[600*OUT_];
__device__ int g_count[B_];

__device__ __forceinline__ float sigm(float x){ return 1.f/(1.f+expf(-x)); }
__device__ __forceinline__ float eluf(float x){ return x>0.f ? x : expm1f(x); }

// ---------------- generic SGEMM 128x128x8, fused epilogues -----------------
// MODE 0: C = A@B (+=C if ACC).  MODE 2: node fused.  MODE 3: edge fused.
template<int MODE, bool ACC>
__global__ void __launch_bounds__(256)
sgemm_k(const float* __restrict__ A, int lda,
        const float* __restrict__ Bm, int ldb,
        float* __restrict__ Cm, int ldc, int Nc, int K,
        const int* __restrict__ batchOf,
        const float* __restrict__ npsim, const float* __restrict__ instrP,
        const float* __restrict__ wvec, float* __restrict__ dotOut,
        const int* __restrict__ srcI, const int* __restrict__ dstI,
        const float* __restrict__ distP)
{
    __shared__ __align__(16) float As[8][128];
    __shared__ __align__(16) float Bs[8][128];
    constexpr int SC = (MODE==2) ? 2400 : 304;
    __shared__ float s_sc[SC];
    const int tid = threadIdx.x;
    const int row0 = blockIdx.y * 128, col0 = blockIdx.x * 128;
    const int tx = tid & 15, ty = tid >> 4;

    if (MODE==2){
        int b = batchOf[row0];
        for (int j=tid; j<2400; j+=256){
            int p = j/300, h = j - p*300;
            s_sc[j] = npsim[b*8+p]*instrP[(size_t)b*1200+h];
        }
    }
    if (MODE==3){
        int b = batchOf[row0];
        for (int j=tid; j<300; j+=256) s_sc[j] = instrP[(size_t)b*1200+j];
    }
    if (MODE==2||MODE==3) __syncthreads();

    float acc[8][8];
    #pragma unroll
    for(int i=0;i<8;i++){
        #pragma unroll
        for(int j=0;j<8;j++) acc[i][j]=0.f;
    }

    const int arow = tid>>1, akq = (tid&1)*4;
    const int brow = tid>>5, bc4 = (tid&31)*4;

    for (int k0=0; k0<K; k0+=8){
        float4 av = make_float4(0.f,0.f,0.f,0.f);
        if (k0 + akq < K)
            av = *reinterpret_cast<const float4*>(A + (size_t)(row0+arow)*lda + k0 + akq);
        if (MODE==2){
            av.x *= s_sc[k0+akq];   av.y *= s_sc[k0+akq+1];
            av.z *= s_sc[k0+akq+2]; av.w *= s_sc[k0+akq+3];
        }
        float4 bv = make_float4(0.f,0.f,0.f,0.f);
        int krow = k0 + brow;
        if (krow < K){
            int c = col0 + bc4;
            const float* bp = Bm + (size_t)krow*ldb;
            if (c + 3 < Nc) bv = *reinterpret_cast<const float4*>(bp + c);
            else {
                if (c  <Nc) bv.x = bp[c];
                if (c+1<Nc) bv.y = bp[c+1];
                if (c+2<Nc) bv.z = bp[c+2];
                if (c+3<Nc) bv.w = bp[c+3];
            }
            if (MODE==3){ float s=s_sc[krow]; bv.x*=s; bv.y*=s; bv.z*=s; bv.w*=s; }
        }
        __syncthreads();
        As[akq+0][arow]=av.x; As[akq+1][arow]=av.y;
        As[akq+2][arow]=av.z; As[akq+3][arow]=av.w;
        *reinterpret_cast<float4*>(&Bs[brow][bc4]) = bv;
        __syncthreads();
        #pragma unroll
        for (int kk=0;kk<8;kk++){
            float ra[8], rb[8];
            #pragma unroll
            for(int i=0;i<8;i++) ra[i]=As[kk][ty+16*i];
            #pragma unroll
            for(int j=0;j<8;j++) rb[j]=Bs[kk][tx+16*j];
            #pragma unroll
            for(int i=0;i<8;i++){
                #pragma unroll
                for(int j=0;j<8;j++) acc[i][j] += ra[i]*rb[j];
            }
        }
    }

    if (MODE==0){
        #pragma unroll
        for(int i=0;i<8;i++){
            int r = row0 + ty + 16*i;
            #pragma unroll
            for(int j=0;j<8;j++){
                int c = col0 + tx + 16*j;
                if (c < Nc){
                    size_t idx = (size_t)r*ldc + c;
                    Cm[idx] = ACC ? (Cm[idx] + acc[i][j]) : acc[i][j];
                }
            }
        }
    } else {
        float wv[8];
        #pragma unroll
        for(int j=0;j<8;j++){
            int c = col0 + tx + 16*j;
            wv[j] = (c<Nc) ? wvec[c] : 0.f;
        }
        #pragma unroll
        for(int i=0;i<8;i++){
            float s = 0.f;
            #pragma unroll
            for(int j=0;j<8;j++){ float v=acc[i][j]; v = v>0.f?v:expm1f(v); s += v*wv[j]; }
            #pragma unroll
            for (int m=1;m<16;m<<=1) s += __shfl_xor_sync(0xffffffffu, s, m);
            if (tx==0){
                int r = row0 + ty + 16*i;
                if (MODE==2) atomicAdd(&dotOut[r], s);
                else         atomicAdd(&dotOut[dstI[r]], distP[srcI[r]]*s);
            }
        }
    }
}

// ---------------- small kernels -----------------
__global__ void transpose_k(const float* __restrict__ src, float* __restrict__ dst, int R, int Cc){
    int idx = blockIdx.x*blockDim.x + threadIdx.x;
    if (idx < R*Cc){ int r=idx/Cc, c=idx-r*Cc; dst[(size_t)c*R + r] = src[idx]; }
}
__global__ void vextT_k(const float* __restrict__ cv, const float* __restrict__ demb){
    int idx = blockIdx.x*blockDim.x + threadIdx.x;
    if (idx < H_*LDSIM){
        int h = idx / LDSIM, c = idx - h*LDSIM;
        float v = 0.f;
        if (c < C_) v = cv[(size_t)c*H_ + h];
        else if (c == C_) v = demb[h];
        g_vextT[idx] = v;
    }
}
__global__ void __launch_bounds__(256) smrow_k(){
    __shared__ float red[256];
    int r = blockIdx.x, t = threadIdx.x;
    float* row = g_sim + (size_t)r*LDSIM;
    float mx = -1e30f;
    for(int c=t;c<2049;c+=256) mx = fmaxf(mx, row[c]);
    red[t]=mx; __syncthreads();
    for(int s=128;s>0;s>>=1){ if(t<s) red[t]=fmaxf(red[t],red[t+s]); __syncthreads(); }
    mx = red[0]; __syncthreads();
    float sm = 0.f;
    for(int c=t;c<2049;c+=256){ float e=expf(row[c]-mx); row[c]=e; sm+=e; }
    red[t]=sm; __syncthreads();
    for(int s=128;s>0;s>>=1){ if(t<s) red[t]+=red[t+s]; __syncthreads(); }
    float inv = 1.f/red[0]; __syncthreads();
    for(int c=t;c<2049;c+=256) row[c]*=inv;
}
__global__ void tagged_init_k(const float* __restrict__ q){
    int idx = blockIdx.x*blockDim.x + threadIdx.x;
    if (idx < B_*L_*H_){
        int r = idx / H_;
        g_tagged[idx] = g_sim[(size_t)r*LDSIM + C_] * q[idx];
    }
}
__global__ void __launch_bounds__(320) lstm_k(const float* __restrict__ bih, const float* __restrict__ bhh){
    __shared__ float h_s[304], c_s[304], z_s[1200];
    int b = blockIdx.x, tid = threadIdx.x;
    if (tid<300){ h_s[tid]=0.f; c_s[tid]=0.f; }
    __syncthreads();
    const float4* W = reinterpret_cast<const float4*>(g_WhhT);
    for (int t=0;t<20;t++){
        if (tid<300){
            int j4 = tid*4;
            float4 a = *reinterpret_cast<const float4*>(&g_Zx[((size_t)b*20+t)*1200 + j4]);
            a.x += bih[j4]+bhh[j4];     a.y += bih[j4+1]+bhh[j4+1];
            a.z += bih[j4+2]+bhh[j4+2]; a.w += bih[j4+3]+bhh[j4+3];
            for(int h=0;h<300;h++){
                float hv = h_s[h];
                float4 w = W[(size_t)h*300 + tid];
                a.x += hv*w.x; a.y += hv*w.y; a.z += hv*w.z; a.w += hv*w.w;
            }
            *reinterpret_cast<float4*>(&z_s[j4]) = a;
        }
        __syncthreads();
        if (tid<300){
            float iv=sigm(z_s[tid]), fv=sigm(z_s[300+tid]);
            float gv=tanhf(z_s[600+tid]), ov=sigm(z_s[900+tid]);
            float c = fv*c_s[tid] + iv*gv;
            c_s[tid]=c; h_s[tid]=ov*tanhf(c);
        }
        __syncthreads();
    }
    if (tid<300) g_h[b*300+tid] = h_s[tid];
}
__global__ void __launch_bounds__(320) rnn_k(const float* __restrict__ rbih, const float* __restrict__ rbhh){
    __shared__ float enc[304], ex[304], hx[304], hn[304];
    int b = blockIdx.x, tid = threadIdx.x;
    if (tid<300) enc[tid]=g_h[b*300+tid];
    __syncthreads();
    if (tid<300){
        float a = rbih[tid]+rbhh[tid];
        for(int k=0;k<300;k++) a += enc[k]*g_rWihT[k*300+tid];
        ex[tid]=a; hx[tid]=0.f;
    }
    __syncthreads();
    for(int it=0; it<4; it++){
        if (tid<300){
            float a = ex[tid];
            for(int k=0;k<300;k++) a += hx[k]*g_rWhhT[k*300+tid];
            a = a>0.f ? a : 0.f;
            hn[tid]=a;
            g_hidden[(size_t)b*1200 + it*300 + tid] = a;
        }
        __syncthreads();
        if (tid<300) hx[tid]=hn[tid];
        __syncthreads();
    }
}
__global__ void __launch_bounds__(256) attn_k(){
    __shared__ float hid[1200], tg[6000], at[80];
    int b = blockIdx.x, tid = threadIdx.x;
    for(int j=tid;j<1200;j+=256) hid[j]=g_hidden[(size_t)b*1200+j];
    for(int j=tid;j<6000;j+=256) tg[j]=g_tagged[(size_t)b*6000+j];
    __syncthreads();
    if (tid<80){
        int i=tid/20, l=tid%20;
        float a=0.f;
        for(int h=0;h<300;h++) a += hid[i*300+h]*tg[l*300+h];
        at[tid]=a;
    }
    __syncthreads();
    if (tid<4){
        float mx=-1e30f;
        for(int l=0;l<20;l++) mx=fmaxf(mx,at[tid*20+l]);
        float s=0.f;
        for(int l=0;l<20;l++){ float e=expf(at[tid*20+l]-mx); at[tid*20+l]=e; s+=e; }
        float inv=1.f/s;
        for(int l=0;l<20;l++) at[tid*20+l]*=inv;
    }
    __syncthreads();
    for(int idx=tid; idx<1200; idx+=256){
        int i=idx/300, h=idx-i*300;
        float a=0.f;
        for(int l=0;l<20;l++) a += at[i*20+l]*tg[l*300+h];
        g_instr[(size_t)b*1200+idx]=a;
    }
}
__global__ void psim_k(const float* __restrict__ pe, int step){
    __shared__ float lg[64][9];
    int tid = threadIdx.x;
    if (tid < 576){
        int b=tid/9, j=tid-b*9;
        const float* ip = g_instr + (size_t)b*1200 + step*300;
        float a=0.f;
        for(int h=0;h<300;h++) a += ip[h]*pe[j*300+h];
        lg[b][j]=a;
    }
    __syncthreads();
    if (tid < 64){
        float mx=-1e30f;
        for(int j=0;j<9;j++) mx=fmaxf(mx,lg[tid][j]);
        float e[9], s=0.f;
        for(int j=0;j<9;j++){ e[j]=expf(lg[tid][j]-mx); s+=e[j]; }
        float inv=1.f/s;
        for(int p=0;p<8;p++) g_npsim[tid*8+p]=e[p]*inv;
        g_rsim[tid]=e[8]*inv;
    }
}
__global__ void zero_misc_k(){
    int idx = blockIdx.x*blockDim.x + threadIdx.x;
    if (idx < B_) g_count[idx]=0;
    if (idx < B_*H_) g_agg[idx]=0.f;
}
__global__ void count_k(const int* __restrict__ ni){
    int n = blockIdx.x*blockDim.x + threadIdx.x;
    if (n < N_) atomicAdd(&g_count[ni[n]], 1);
}
__global__ void distinit_k(const int* __restrict__ ni){
    int n = blockIdx.x*blockDim.x + threadIdx.x;
    if (n < N_) g_dist[n] = 1.f/(float)g_count[ni[n]];
}
__global__ void zerodots_k(){
    int n = blockIdx.x*blockDim.x + threadIdx.x;
    if (n < N_){ g_dotns[n]=0.f; g_dotnr[n]=0.f; }
}
__global__ void __launch_bounds__(512) segsm_k(){
    __shared__ float red[512];
    int b = blockIdx.x, t = threadIdx.x;
    int n = b*512 + t;
    float v1 = g_dotns[n], v2 = g_dotnr[n];
    red[t]=v1; __syncthreads();
    for(int s=256;s>0;s>>=1){ if(t<s) red[t]=fmaxf(red[t],red[t+s]); __syncthreads(); }
    float m1=red[0]; __syncthreads();
    float e1=expf(v1-m1);
    red[t]=e1; __syncthreads();
    for(int s=256;s>0;s>>=1){ if(t<s) red[t]+=red[t+s]; __syncthreads(); }
    float s1=red[0]; __syncthreads();
    red[t]=v2; __syncthreads();
    for(int s=256;s>0;s>>=1){ if(t<s) red[t]=fmaxf(red[t],red[t+s]); __syncthreads(); }
    float m2=red[0]; __syncthreads();
    float e2=expf(v2-m2);
    red[t]=e2; __syncthreads();
    for(int s=256;s>0;s>>=1){ if(t<s) red[t]+=red[t+s]; __syncthreads(); }
    float s2=red[0];
    float rs = g_rsim[b];
    g_dist[n] = rs*(e2/s2) + (1.f-rs)*(e1/s1);
}
__global__ void __launch_bounds__(320) agg_k(const float* __restrict__ attrs, const int* __restrict__ ni){
    __shared__ float np_s[8], d_s[64];
    int blk = blockIdx.x, tid = threadIdx.x;
    int n0 = blk*64;
    int b = ni[n0];
    if (tid<8)  np_s[tid] = g_npsim[b*8+tid];
    if (tid<64) d_s[tid]  = g_dist[n0+tid];
    __syncthreads();
    if (tid<300){
        float acc = 0.f;
        for(int n=0;n<64;n++){
            const float* ap = attrs + (size_t)(n0+n)*2400 + tid;
            float s = 0.f;
            #pragma unroll
            for(int p=0;p<8;p++) s += np_s[p]*ap[p*300];
            acc += d_s[n]*s;
        }
        atomicAdd(&g_agg[b*300+tid], acc);
    }
}
__global__ void __launch_bounds__(256) fc_k(const float* __restrict__ fc1b,
                                            const float* __restrict__ fc2b,
                                            float* __restrict__ out){
    __shared__ float ft[600], h1[600];
    int b = blockIdx.x, tid = threadIdx.x;
    for(int j=tid;j<300;j+=256){ ft[j]=g_h[b*300+j]; ft[300+j]=g_agg[b*300+j]; }
    __syncthreads();
    for(int j=tid;j<600;j+=256){
        float a = fc1b[j];
        for(int k=0;k<600;k++) a += ft[k]*g_fc1T[k*600+j];
        h1[j] = eluf(a);
    }
    __syncthreads();
    for(int o=tid;o<OUT_;o+=256){
        float a = fc2b[o];
        for(int k=0;k<600;k++) a += h1[k]*g_fc2T[(size_t)k*OUT_+o];
        out[(size_t)b*OUT_+o]=a;
    }
}

// ---------------- driver -----------------
extern "C" void kernel_launch(void* const* d_in, const int* in_sizes, int n_in,
                              void* d_out, int out_size) {
    const float* questions = (const float*)d_in[0];
    const float* cv        = (const float*)d_in[1];
    const float* pe        = (const float*)d_in[2];
    const float* attrs     = (const float*)d_in[3];
    const float* eattrs    = (const float*)d_in[4];
    const float* wtag      = (const float*)d_in[5];
    const float* demb      = (const float*)d_in[6];
    const float* lWih      = (const float*)d_in[7];
    const float* lWhh      = (const float*)d_in[8];
    const float* lbih      = (const float*)d_in[9];
    const float* lbhh      = (const float*)d_in[10];
    const float* rWih      = (const float*)d_in[11];
    const float* rWhh      = (const float*)d_in[12];
    const float* rbih      = (const float*)d_in[13];
    const float* rbhh      = (const float*)d_in[14];
    const float* Wp        = (const float*)d_in[15];
    const float* We        = (const float*)d_in[16];
    const float* w_ns      = (const float*)d_in[17];
    const float* w_rs      = (const float*)d_in[18];
    const float* fc1w      = (const float*)d_in[19];
    const float* fc1b      = (const float*)d_in[20];
    const float* fc2w      = (const float*)d_in[21];
    const float* fc2b      = (const float*)d_in[22];
    const int*   ni        = (const int*)d_in[23];
    const int*   esrc      = (const int*)d_in[24];
    const int*   edst      = (const int*)d_in[25];
    const int*   ebatch    = (const int*)d_in[26];
    float* out = (float*)d_out;

    float *WihT, *WhhT, *rWihT, *rWhhT, *fc1T, *fc2T;
    float *qt, *sim, *vextT, *tagged, *Zx, *npsimP, *instrP0;
    float *dotns, *dotnr, *distP;
    cudaGetSymbolAddress((void**)&WihT,  g_WihT);
    cudaGetSymbolAddress((void**)&WhhT,  g_WhhT);
    cudaGetSymbolAddress((void**)&rWihT, g_rWihT);
    cudaGetSymbolAddress((void**)&rWhhT, g_rWhhT);
    cudaGetSymbolAddress((void**)&fc1T,  g_fc1T);
    cudaGetSymbolAddress((void**)&fc2T,  g_fc2T);
    cudaGetSymbolAddress((void**)&qt,    g_qt);
    cudaGetSymbolAddress((void**)&sim,   g_sim);
    cudaGetSymbolAddress((void**)&vextT, g_vextT);
    cudaGetSymbolAddress((void**)&tagged,g_tagged);
    cudaGetSymbolAddress((void**)&Zx,    g_Zx);
    cudaGetSymbolAddress((void**)&npsimP,g_npsim);
    cudaGetSymbolAddress((void**)&instrP0,g_instr);
    cudaGetSymbolAddress((void**)&dotns, g_dotns);
    cudaGetSymbolAddress((void**)&dotnr, g_dotnr);
    cudaGetSymbolAddress((void**)&distP, g_dist);

    // transposes
    transpose_k<<<CDIV(1200*300,256),256>>>(lWih, WihT, 1200, 300);
    transpose_k<<<CDIV(1200*300,256),256>>>(lWhh, WhhT, 1200, 300);
    transpose_k<<<CDIV(300*300,256),256>>>(rWih, rWihT, 300, 300);
    transpose_k<<<CDIV(300*300,256),256>>>(rWhh, rWhhT, 300, 300);
    transpose_k<<<CDIV(600*600,256),256>>>(fc1w, fc1T, 600, 600);
    transpose_k<<<CDIV(OUT_*600,256),256>>>(fc2w, fc2T, OUT_, 600);
    vextT_k<<<CDIV(H_*LDSIM,256),256>>>(cv, demb);
    zero_misc_k<<<CDIV(B_*H_,256),256>>>();
    count_k<<<CDIV(N_,256),256>>>(ni);
    distinit_k<<<CDIV(N_,256),256>>>(ni);

    // tagging
    sgemm_k<0,false><<<dim3(CDIV(300,128),10),256>>>(questions,300, wtag,300, qt,300, 300,300,
        0,0,0,0,0,0,0,0);
    sgemm_k<0,false><<<dim3(CDIV(2049,128),10),256>>>(qt,300, vextT,LDSIM, sim,LDSIM, 2049,300,
        0,0,0,0,0,0,0,0);
    smrow_k<<<B_*L_,256>>>();
    tagged_init_k<<<CDIV(B_*L_*H_,256),256>>>(questions);
    sgemm_k<0,true><<<dim3(CDIV(300,128),10),256>>>(sim,LDSIM, cv,300, tagged,300, 300,2048,
        0,0,0,0,0,0,0,0);

    // LSTM + RNN + attn
    sgemm_k<0,false><<<dim3(CDIV(1200,128),10),256>>>(tagged,300, WihT,1200, Zx,1200, 1200,300,
        0,0,0,0,0,0,0,0);
    lstm_k<<<B_,320>>>(lbih, lbhh);
    rnn_k<<<B_,320>>>(rbih, rbhh);
    attn_k<<<B_,256>>>();

    // reasoning steps
    for (int step=0; step<3; step++){
        psim_k<<<1,576>>>(pe, step);
        zerodots_k<<<CDIV(N_,256),256>>>();
        sgemm_k<2,false><<<dim3(CDIV(300,128), N_/128),256>>>(attrs,2400, Wp,300,
            (float*)0,0, 300,2400, ni, npsimP, instrP0+step*300, w_ns, dotns, 0,0,0);
        sgemm_k<3,false><<<dim3(CDIV(300,128), E_/128),256>>>(eattrs,300, We,300,
            (float*)0,0, 300,300, ebatch, 0, instrP0+step*300, w_rs, dotnr, esrc, edst, distP);
        segsm_k<<<B_,512>>>();
    }

    // final aggregation + MLP
    psim_k<<<1,576>>>(pe, 3);
    agg_k<<<N_/64,320>>>(attrs, ni);
    fc_k<<<B_,256>>>(fc1b, fc2b, out);
}